// round 9
// baseline (speedup 1.0000x reference)
#include <cuda_runtime.h>
#include <cuda_bf16.h>
#include <math.h>
#include <stdint.h>

#define BB 2
#define NNODES 4096
#define DIMF 128
#define KNN 32
#define HID 530
#define EPAD 544                    // padded hidden (17*32)
#define NODES (BB*NNODES)           // 8192
#define NODE_OUT_ELEMS (NODES*DIMF)

typedef unsigned long long ull;

// ---------------- scratch (static device arrays; no allocation) -------------
__device__ float g_A[NODES * EPAD];    // feats@We1[0:128]+be1 (pad cols zero)
__device__ float g_B[NODES * EPAD];    // feats@We1[128:256]   (pad cols zero)
__device__ float g_XC[NODES * 144];    // [feats | m_i]
__device__ float g_H1[NODES * 256];    // node hidden
__device__ int   g_knn[NODES * KNN];

// ---------------- f32x2 helpers ---------------------------------------------
__device__ __forceinline__ ull pack2(float lo, float hi) {
    ull u; asm("mov.b64 %0, {%1, %2};" : "=l"(u) : "f"(lo), "f"(hi)); return u;
}
__device__ __forceinline__ float2 unpack2(ull u) {
    float2 v; asm("mov.b64 {%0, %1}, %2;" : "=f"(v.x), "=f"(v.y) : "l"(u)); return v;
}
__device__ __forceinline__ void ffma2(ull& d, ull a, ull b) {
    asm("fma.rn.f32x2 %0, %1, %2, %0;" : "+l"(d) : "l"(a), "l"(b));
}
__device__ __forceinline__ ull fadd2(ull a, ull b) {
    ull d; asm("add.rn.f32x2 %0, %1, %2;" : "=l"(d) : "l"(a), "l"(b)); return d;
}

__device__ __forceinline__ float silu_f(float x) {
    float e = __expf(-x);
    return __fdividef(x, 1.0f + e);
}

__device__ __forceinline__ float dist2_f(float dx, float dy, float dz) {
    return __fadd_rn(__fadd_rn(__fmul_rn(dx, dx), __fmul_rn(dy, dy)), __fmul_rn(dz, dz));
}

// ---------------------------------------------------------------------------
// KNN: one warp per (b,i). Unsorted top-32 set via warp REDUX threshold.
// ---------------------------------------------------------------------------
__global__ __launch_bounds__(256) void knn_kernel(const float* __restrict__ coors) {
    const unsigned FULL = 0xffffffffu;
    int w    = blockIdx.x * 8 + (threadIdx.x >> 5);
    int lane = threadIdx.x & 31;
    int b = w >> 12;
    int i = w & (NNODES - 1);
    const float* cb = coors + (size_t)b * NNODES * 3;
    float qx = cb[3 * i + 0], qy = cb[3 * i + 1], qz = cb[3 * i + 2];

    float dx = qx - cb[3 * lane + 0];
    float dy = qy - cb[3 * lane + 1];
    float dz = qz - cb[3 * lane + 2];
    unsigned bu = __float_as_uint(dist2_f(dx, dy, dz));
    int bj = lane;
    unsigned curmax = __reduce_max_sync(FULL, bu);

    for (int j0 = 32; j0 < NNODES; j0 += 32) {
        int j = j0 + lane;
        float ex = qx - cb[3 * j + 0];
        float ey = qy - cb[3 * j + 1];
        float ez = qz - cb[3 * j + 2];
        unsigned du = __float_as_uint(dist2_f(ex, ey, ez));
        unsigned mask = __ballot_sync(FULL, du < curmax);
        while (mask) {
            int src = __ffs(mask) - 1;
            mask &= mask - 1;
            unsigned dc = __shfl_sync(FULL, du, src);
            if (dc < curmax) {
                unsigned mm = __ballot_sync(FULL, bu == curmax);
                int ml = __ffs(mm) - 1;
                if (lane == ml) { bu = dc; bj = j0 + src; }
                curmax = __reduce_max_sync(FULL, bu);
            }
        }
    }
    g_knn[(size_t)w * KNN + lane] = bj;
}

// ---------------------------------------------------------------------------
// Tiled fp32 GEMM (FFMA2): C[.. x Npad] = act(X @ W + b) (+resid); pads -> 0
// ---------------------------------------------------------------------------
__global__ __launch_bounds__(256) void gemm_kernel(
    const float* __restrict__ X, int ldx,
    const float* __restrict__ W, int ldw,
    const float* __restrict__ bias,
    const float* __restrict__ resid, int ldr,
    float* __restrict__ C, int ldc,
    int Nw, int Npad, int K, int act)
{
    __shared__ float Xs[16][68];
    __shared__ float Ws[16][68];
    int tid = threadIdx.x;
    int tx = tid & 15, ty = tid >> 4;
    int m0 = blockIdx.y * 64, n0 = blockIdx.x * 64;

    int lm  = tid >> 2;
    int lk  = (tid & 3) * 4;
    int wn  = tid & 63;
    int wkb = (tid >> 6) * 4;

    ull acc2[4][2];
#pragma unroll
    for (int a = 0; a < 4; a++) { acc2[a][0] = 0ull; acc2[a][1] = 0ull; }

    for (int kt = 0; kt < K; kt += 16) {
        float4 xv = *reinterpret_cast<const float4*>(X + (size_t)(m0 + lm) * ldx + kt + lk);
        Xs[lk + 0][lm] = xv.x;
        Xs[lk + 1][lm] = xv.y;
        Xs[lk + 2][lm] = xv.z;
        Xs[lk + 3][lm] = xv.w;
#pragma unroll
        for (int q = 0; q < 4; q++) {
            int k = wkb + q;
            float v = (n0 + wn < Nw) ? W[(size_t)(kt + k) * ldw + n0 + wn] : 0.f;
            Ws[k][wn] = v;
        }
        __syncthreads();
#pragma unroll
        for (int k = 0; k < 16; k++) {
            float4 a4 = *reinterpret_cast<const float4*>(&Xs[k][ty * 4]);
            float4 b4 = *reinterpret_cast<const float4*>(&Ws[k][tx * 4]);
            ull b01 = pack2(b4.x, b4.y);
            ull b23 = pack2(b4.z, b4.w);
            float av[4] = {a4.x, a4.y, a4.z, a4.w};
#pragma unroll
            for (int mi = 0; mi < 4; mi++) {
                ull aa = pack2(av[mi], av[mi]);
                ffma2(acc2[mi][0], aa, b01);
                ffma2(acc2[mi][1], aa, b23);
            }
        }
        __syncthreads();
    }

#pragma unroll
    for (int mi = 0; mi < 4; mi++) {
        int m = m0 + ty * 4 + mi;
        float2 lo = unpack2(acc2[mi][0]);
        float2 hi = unpack2(acc2[mi][1]);
        float accv[4] = {lo.x, lo.y, hi.x, hi.y};
#pragma unroll
        for (int ni = 0; ni < 4; ni++) {
            int n = n0 + tx * 4 + ni;
            if (n < Npad) {
                float v = accv[ni];
                if (n < Nw) {
                    if (bias) v += bias[n];
                    if (act) v = silu_f(v);
                    if (resid) v += resid[(size_t)m * ldr + n];
                } else {
                    v = 0.f;
                }
                C[(size_t)m * ldc + n] = v;
            }
        }
    }
}

// ---------------------------------------------------------------------------
__global__ __launch_bounds__(256) void copy_feats_kernel(const float* __restrict__ feats) {
    int idx = blockIdx.x * 256 + threadIdx.x;  // over NODES*128
    int n = idx >> 7, c = idx & 127;
    g_XC[(size_t)n * 144 + c] = feats[idx];
}

// ---------------------------------------------------------------------------
// Edge kernel, TRANSPOSED ownership: 256 threads (8 warps), 4 nodes/block.
// Warp w owns channel slice [w*34, w*34+34) of each 272-channel half;
// lane l owns edge l. Weights broadcast-read once per channel, reused for all
// 32 edges. B rows staged per node into SB[32][273] (odd stride -> conflict-
// free column reads). m[16] per lane accumulates in registers across all
// channels; one 8-warp partial reduction per node (overlaid on dead SB).
// ---------------------------------------------------------------------------
// byte offsets in dynamic smem:
#define OFF_WE2  0                                // ulonglong2[544*4] = 34816
#define OFF_W9A  34816                            // ulonglong2[544*2] = 17408
#define OFF_W9B  52224                            // ull[544]          = 4352
#define OFF_AS   56576                            // float[544]        = 2176
#define OFF_F2   58752                            // ull[32*6]         = 1536
#define OFF_SB   60288                            // float[32*273]=34944 (overlay: mpart ull[256*9]=18432)
#define OFF_FLT  95232
#define FI_WC1 0
#define FI_BC1 1024
#define FI_WC2 1088
#define FI_BE2 1152
#define FI_RC  1168
#define FI_MS  1296
#define FI_CW  1808
#define FI_EBO 1840
#define FI_TOT 1872
#define EK_SMEM_BYTES (OFF_FLT + FI_TOT*4)        // 102720

__global__ __launch_bounds__(256, 2) void edge_kernel(
    const float* __restrict__ coors,
    const float* __restrict__ We1,
    const float* __restrict__ We2,
    const float* __restrict__ be2,
    const float* __restrict__ Wc1,
    const float* __restrict__ bc1,
    const float* __restrict__ Wc2,
    const float* __restrict__ bc2,
    float* __restrict__ coors_out)
{
    extern __shared__ char smc[];
    ulonglong2* We2q = (ulonglong2*)(smc + OFF_WE2);   // [c*4+p] -> outputs 4p..4p+3
    ulonglong2* W9A  = (ulonglong2*)(smc + OFF_W9A);   // [c*2+t] -> fourier terms 4t..4t+3
    ull* W9B = (ull*)(smc + OFF_W9B);                  // [c] -> (term8, 0)
    float* As  = (float*)(smc + OFF_AS);
    ull* F2u = (ull*)(smc + OFF_F2);                   // [32][6] per-edge fourier pairs
    float* SB  = (float*)(smc + OFF_SB);               // [32][273] staged B half-rows
    ull* mpart = (ull*)(smc + OFF_SB);                 // overlay: [256][9] partial m
    float* smf  = (float*)(smc + OFF_FLT);
    float* Wc1s = smf + FI_WC1;
    float* bc1s = smf + FI_BC1;
    float* Wc2s = smf + FI_WC2;
    float* be2s = smf + FI_BE2;
    float* rc_s = smf + FI_RC;                         // [32][4]
    float* ms   = smf + FI_MS;                         // [32][16]
    float* cw_s = smf + FI_CW;                         // [32]
    uint32_t* ebo_s = (uint32_t*)(smf + FI_EBO);       // [32]

    int tid = threadIdx.x;
    int w = tid >> 5, lane = tid & 31;
    const unsigned FULL = 0xffffffffu;
    float bc2v = bc2[0];

    // ---- weight preamble (once per block) ----
    for (int idx = tid; idx < 4 * EPAD; idx += 256) {
        int c = idx >> 2, p = idx & 3;
        ulonglong2 v; v.x = 0ull; v.y = 0ull;
        if (c < HID) {
            v.x = pack2(We2[c * 16 + 4 * p + 0], We2[c * 16 + 4 * p + 1]);
            v.y = pack2(We2[c * 16 + 4 * p + 2], We2[c * 16 + 4 * p + 3]);
        }
        We2q[idx] = v;
    }
    for (int idx = tid; idx < 2 * EPAD; idx += 256) {
        int c = idx >> 1, t = idx & 1;
        ulonglong2 v; v.x = 0ull; v.y = 0ull;
        if (c < HID) {
            v.x = pack2(We1[(size_t)(256 + 4 * t + 0) * HID + c], We1[(size_t)(256 + 4 * t + 1) * HID + c]);
            v.y = pack2(We1[(size_t)(256 + 4 * t + 2) * HID + c], We1[(size_t)(256 + 4 * t + 3) * HID + c]);
        }
        W9A[idx] = v;
    }
    for (int c = tid; c < EPAD; c += 256) {
        ull v = 0ull;
        if (c < HID) v = pack2(We1[(size_t)264 * HID + c], 0.f);
        W9B[c] = v;
    }
    for (int idx = tid; idx < 16 * 64; idx += 256) Wc1s[idx] = Wc1[idx];
    if (tid < 64) { bc1s[tid] = bc1[tid]; Wc2s[tid] = Wc2[tid]; }
    if (tid >= 64 && tid < 80) be2s[tid - 64] = be2[tid - 64];
    __syncthreads();

#pragma unroll 1
    for (int nn = 0; nn < 4; nn++) {
        int node = blockIdx.x * 4 + nn;
        int b = node >> 12, i = node & (NNODES - 1);
        const float* cb = coors + (size_t)b * NNODES * 3;
        const float* Ap = g_A + (size_t)node * EPAD;

        // ---- per-node setup: A row, fourier pairs, rel coords, B offsets ----
        for (int idx = tid; idx < EPAD; idx += 256) As[idx] = Ap[idx];
        if (tid < 32) {
            int e = tid;
            int j = g_knn[(size_t)node * KNN + e];
            ebo_s[e] = (uint32_t)(b * NNODES + j);
            float dx = cb[3 * i + 0] - cb[3 * j + 0];
            float dy = cb[3 * i + 1] - cb[3 * j + 1];
            float dz = cb[3 * i + 2] - cb[3 * j + 2];
            float d = dist2_f(dx, dy, dz);
            rc_s[e * 4 + 0] = dx; rc_s[e * 4 + 1] = dy; rc_s[e * 4 + 2] = dz; rc_s[e * 4 + 3] = 0.f;
            float s0, c0, s1, c1, s2, c2, s3, c3;
            sincosf(d,          &s0, &c0);
            sincosf(d * 0.5f,   &s1, &c1);
            sincosf(d * 0.25f,  &s2, &c2);
            sincosf(d * 0.125f, &s3, &c3);
            F2u[e * 6 + 0] = pack2(s0, s1);
            F2u[e * 6 + 1] = pack2(s2, s3);
            F2u[e * 6 + 2] = pack2(c0, c1);
            F2u[e * 6 + 3] = pack2(c2, c3);
            F2u[e * 6 + 4] = pack2(d, 0.f);
        }
        __syncthreads();

        // lane owns edge = lane: fourier pairs live in registers all node long
        ull fp[5];
#pragma unroll
        for (int t = 0; t < 5; t++) fp[t] = F2u[lane * 6 + t];

        ull m[8];
#pragma unroll
        for (int p = 0; p < 8; p++) m[p] = 0ull;

#pragma unroll 1
        for (int half = 0; half < 2; half++) {
            // ---- stage B half-rows: SB[e][q] = g_B[row_e][half*272+q] ----
            for (int idx = tid; idx < 32 * 272; idx += 256) {
                int e = idx / 272, q = idx - e * 272;
                SB[e * 273 + q] = g_B[(size_t)ebo_s[e] * EPAD + half * 272 + q];
            }
            __syncthreads();

            // ---- compute: warp w owns channels [w*34, w*34+34) of this half
            int hc0 = w * 34;
#pragma unroll 2
            for (int hc = 0; hc < 34; hc++) {
                int sc = hc0 + hc;            // channel within half (SB column)
                int c  = half * 272 + sc;     // global channel
                float av = As[c];             // broadcast
                float bv = SB[lane * 273 + sc];  // conflict-free column read
                ulonglong2 w9a0 = W9A[c * 2 + 0];
                ulonglong2 w9a1 = W9A[c * 2 + 1];
                ull        w9b  = W9B[c];

                ull ha = pack2(av + bv, 0.f);
                ull hb = 0ull;
                ffma2(ha, fp[0], w9a0.x);
                ffma2(hb, fp[1], w9a0.y);
                ffma2(ha, fp[2], w9a1.x);
                ffma2(hb, fp[3], w9a1.y);
                ffma2(ha, fp[4], w9b);
                float2 hv = unpack2(fadd2(ha, hb));
                float sh = silu_f(hv.x + hv.y);
                ull shp = pack2(sh, sh);

                ulonglong2 q0 = We2q[c * 4 + 0];
                ulonglong2 q1 = We2q[c * 4 + 1];
                ulonglong2 q2 = We2q[c * 4 + 2];
                ulonglong2 q3 = We2q[c * 4 + 3];
                ffma2(m[0], shp, q0.x); ffma2(m[1], shp, q0.y);
                ffma2(m[2], shp, q1.x); ffma2(m[3], shp, q1.y);
                ffma2(m[4], shp, q2.x); ffma2(m[5], shp, q2.y);
                ffma2(m[6], shp, q3.x); ffma2(m[7], shp, q3.y);
            }
            __syncthreads();   // SB dead (half0: restage; half1: mpart overlay)
        }

        // ---- write partial m (overlay on SB region) ----
        {
            int base = (w * 32 + lane) * 9;
#pragma unroll
            for (int p = 0; p < 8; p++) mpart[base + p] = m[p];
        }
        __syncthreads();

        // ---- 8-way cross-warp reduction -> ms ----
        {
            int e = tid >> 3, p = tid & 7;
            ull s = mpart[(0 * 32 + e) * 9 + p];
#pragma unroll
            for (int ww = 1; ww < 8; ww++) s = fadd2(s, mpart[(ww * 32 + e) * 9 + p]);
            float2 v = unpack2(s);
            ms[e * 16 + 2 * p + 0] = silu_f(v.x + be2s[2 * p + 0]);
            ms[e * 16 + 2 * p + 1] = silu_f(v.y + be2s[2 * p + 1]);
        }
        __syncthreads();

        // ---- coors MLP: 8 threads per edge ----
        {
            int e = tid >> 3, li = tid & 7;
            float wpart = 0.f;
#pragma unroll
            for (int q = 0; q < 8; q++) {
                int l = li * 8 + q;
                float u = bc1s[l];
#pragma unroll
                for (int k = 0; k < 16; k++)
                    u = fmaf(ms[e * 16 + k], Wc1s[k * 64 + l], u);
                wpart = fmaf(silu_f(u), Wc2s[l], wpart);
            }
            wpart += __shfl_xor_sync(FULL, wpart, 1);
            wpart += __shfl_xor_sync(FULL, wpart, 2);
            wpart += __shfl_xor_sync(FULL, wpart, 4);
            if (li == 0) cw_s[e] = wpart + bc2v;
        }
        __syncthreads();

        // ---- m_i (threads 0-15) and coors_out (warp 1) ----
        if (tid < 16) {
            float s = 0.f;
#pragma unroll 8
            for (int e2 = 0; e2 < 32; e2++) s += ms[e2 * 16 + tid];
            g_XC[(size_t)node * 144 + 128 + tid] = s;
        }
        if (w == 1) {
            int e2 = lane;
            float wv = cw_s[e2];
            float px = wv * rc_s[e2 * 4 + 0];
            float py = wv * rc_s[e2 * 4 + 1];
            float pz = wv * rc_s[e2 * 4 + 2];
#pragma unroll
            for (int off = 16; off > 0; off >>= 1) {
                px += __shfl_down_sync(FULL, px, off);
                py += __shfl_down_sync(FULL, py, off);
                pz += __shfl_down_sync(FULL, pz, off);
            }
            if (lane == 0) {
                float* co = coors_out + (size_t)node * 3;
                co[0] = cb[3 * i + 0] + px;
                co[1] = cb[3 * i + 1] + py;
                co[2] = cb[3 * i + 2] + pz;
            }
        }
        __syncthreads();
    }
}

// ---------------------------------------------------------------------------
extern "C" void kernel_launch(void* const* d_in, const int* in_sizes, int n_in,
                              void* d_out, int out_size) {
    const float* feats = (const float*)d_in[0];
    const float* coors = (const float*)d_in[1];
    const float* We1   = (const float*)d_in[2];
    const float* be1   = (const float*)d_in[3];
    const float* We2   = (const float*)d_in[4];
    const float* be2   = (const float*)d_in[5];
    const float* Wc1   = (const float*)d_in[6];
    const float* bc1   = (const float*)d_in[7];
    const float* Wc2   = (const float*)d_in[8];
    const float* bc2   = (const float*)d_in[9];
    const float* Wn1   = (const float*)d_in[10];
    const float* bn1   = (const float*)d_in[11];
    const float* Wn2   = (const float*)d_in[12];
    const float* bn2   = (const float*)d_in[13];
    float* out = (float*)d_out;
    float* node_out  = out;
    float* coors_out = out + NODE_OUT_ELEMS;

    float *pA, *pB, *pXC, *pH1;
    cudaGetSymbolAddress((void**)&pA, g_A);
    cudaGetSymbolAddress((void**)&pB, g_B);
    cudaGetSymbolAddress((void**)&pXC, g_XC);
    cudaGetSymbolAddress((void**)&pH1, g_H1);

    cudaFuncSetAttribute(edge_kernel, cudaFuncAttributeMaxDynamicSharedMemorySize, EK_SMEM_BYTES);

    // 1) KNN
    knn_kernel<<<NODES / 8, 256>>>(coors);

    // 2) A = feats @ We1[0:128,:] + be1 ; B = feats @ We1[128:256,:]  (pad->544)
    gemm_kernel<<<dim3(9, NODES / 64), 256>>>(feats, DIMF, We1, HID, be1, nullptr, 0,
                                              pA, EPAD, HID, EPAD, DIMF, 0);
    gemm_kernel<<<dim3(9, NODES / 64), 256>>>(feats, DIMF, We1 + 128 * HID, HID, nullptr, nullptr, 0,
                                              pB, EPAD, HID, EPAD, DIMF, 0);

    // 3) edges: m_ij -> m_i (XC[:,128:144]), coors_out
    edge_kernel<<<NODES / 4, 256, EK_SMEM_BYTES>>>(coors, We1, We2, be2,
                                                   Wc1, bc1, Wc2, bc2, coors_out);

    // 4) XC[:, 0:128] = feats
    copy_feats_kernel<<<(NODES * DIMF) / 256, 256>>>(feats);

    // 5) node MLP
    gemm_kernel<<<dim3(4, NODES / 64), 256>>>(pXC, 144, Wn1, 256, bn1, nullptr, 0,
                                              pH1, 256, 256, 256, 144, 1);
    gemm_kernel<<<dim3(2, NODES / 64), 256>>>(pH1, 256, Wn2, DIMF, bn2, feats, DIMF,
                                              node_out, DIMF, DIMF, DIMF, 256, 0);
}

// round 10
// speedup vs baseline: 1.3375x; 1.3375x over previous
#include <cuda_runtime.h>
#include <cuda_bf16.h>
#include <math.h>
#include <stdint.h>

#define BB 2
#define NNODES 4096
#define DIMF 128
#define KNN 32
#define HID 530
#define EPAD 544                    // padded hidden (17*32)
#define NODES (BB*NNODES)           // 8192
#define NODE_OUT_ELEMS (NODES*DIMF)

typedef unsigned long long ull;

// ---------------- scratch (static device arrays; no allocation) -------------
__device__ float g_A[NODES * EPAD];    // feats@We1[0:128]+be1 (pad cols zero)
__device__ float g_B[NODES * EPAD];    // feats@We1[128:256]   (pad cols zero)
__device__ float g_XC[NODES * 144];    // [feats | m_i]
__device__ float g_H1[NODES * 256];    // node hidden
__device__ int   g_knn[NODES * KNN];

// ---------------- f32x2 helpers ---------------------------------------------
__device__ __forceinline__ ull pack2(float lo, float hi) {
    ull u; asm("mov.b64 %0, {%1, %2};" : "=l"(u) : "f"(lo), "f"(hi)); return u;
}
__device__ __forceinline__ float2 unpack2(ull u) {
    float2 v; asm("mov.b64 {%0, %1}, %2;" : "=f"(v.x), "=f"(v.y) : "l"(u)); return v;
}
__device__ __forceinline__ void ffma2(ull& d, ull a, ull b) {
    asm("fma.rn.f32x2 %0, %1, %2, %0;" : "+l"(d) : "l"(a), "l"(b));
}
__device__ __forceinline__ ull fadd2(ull a, ull b) {
    ull d; asm("add.rn.f32x2 %0, %1, %2;" : "=l"(d) : "l"(a), "l"(b)); return d;
}

__device__ __forceinline__ float silu_f(float x) {
    float e = __expf(-x);
    return __fdividef(x, 1.0f + e);
}

__device__ __forceinline__ float dist2_f(float dx, float dy, float dz) {
    return __fadd_rn(__fadd_rn(__fmul_rn(dx, dx), __fmul_rn(dy, dy)), __fmul_rn(dz, dz));
}

// ---------------------------------------------------------------------------
// KNN: one warp per (b,i). Unsorted top-32 set via warp REDUX threshold.
// ---------------------------------------------------------------------------
__global__ __launch_bounds__(256) void knn_kernel(const float* __restrict__ coors) {
    const unsigned FULL = 0xffffffffu;
    int w    = blockIdx.x * 8 + (threadIdx.x >> 5);
    int lane = threadIdx.x & 31;
    int b = w >> 12;
    int i = w & (NNODES - 1);
    const float* cb = coors + (size_t)b * NNODES * 3;
    float qx = cb[3 * i + 0], qy = cb[3 * i + 1], qz = cb[3 * i + 2];

    float dx = qx - cb[3 * lane + 0];
    float dy = qy - cb[3 * lane + 1];
    float dz = qz - cb[3 * lane + 2];
    unsigned bu = __float_as_uint(dist2_f(dx, dy, dz));
    int bj = lane;
    unsigned curmax = __reduce_max_sync(FULL, bu);

    for (int j0 = 32; j0 < NNODES; j0 += 32) {
        int j = j0 + lane;
        float ex = qx - cb[3 * j + 0];
        float ey = qy - cb[3 * j + 1];
        float ez = qz - cb[3 * j + 2];
        unsigned du = __float_as_uint(dist2_f(ex, ey, ez));
        unsigned mask = __ballot_sync(FULL, du < curmax);
        while (mask) {
            int src = __ffs(mask) - 1;
            mask &= mask - 1;
            unsigned dc = __shfl_sync(FULL, du, src);
            if (dc < curmax) {
                unsigned mm = __ballot_sync(FULL, bu == curmax);
                int ml = __ffs(mm) - 1;
                if (lane == ml) { bu = dc; bj = j0 + src; }
                curmax = __reduce_max_sync(FULL, bu);
            }
        }
    }
    g_knn[(size_t)w * KNN + lane] = bj;
}

// ---------------------------------------------------------------------------
// Tiled fp32 GEMM (FFMA2): C[.. x Npad] = act(X @ W + b) (+resid); pads -> 0
// ---------------------------------------------------------------------------
__global__ __launch_bounds__(256) void gemm_kernel(
    const float* __restrict__ X, int ldx,
    const float* __restrict__ W, int ldw,
    const float* __restrict__ bias,
    const float* __restrict__ resid, int ldr,
    float* __restrict__ C, int ldc,
    int Nw, int Npad, int K, int act)
{
    __shared__ float Xs[16][68];
    __shared__ float Ws[16][68];
    int tid = threadIdx.x;
    int tx = tid & 15, ty = tid >> 4;
    int m0 = blockIdx.y * 64, n0 = blockIdx.x * 64;

    int lm  = tid >> 2;
    int lk  = (tid & 3) * 4;
    int wn  = tid & 63;
    int wkb = (tid >> 6) * 4;

    ull acc2[4][2];
#pragma unroll
    for (int a = 0; a < 4; a++) { acc2[a][0] = 0ull; acc2[a][1] = 0ull; }

    for (int kt = 0; kt < K; kt += 16) {
        float4 xv = *reinterpret_cast<const float4*>(X + (size_t)(m0 + lm) * ldx + kt + lk);
        Xs[lk + 0][lm] = xv.x;
        Xs[lk + 1][lm] = xv.y;
        Xs[lk + 2][lm] = xv.z;
        Xs[lk + 3][lm] = xv.w;
#pragma unroll
        for (int q = 0; q < 4; q++) {
            int k = wkb + q;
            float v = (n0 + wn < Nw) ? W[(size_t)(kt + k) * ldw + n0 + wn] : 0.f;
            Ws[k][wn] = v;
        }
        __syncthreads();
#pragma unroll
        for (int k = 0; k < 16; k++) {
            float4 a4 = *reinterpret_cast<const float4*>(&Xs[k][ty * 4]);
            float4 b4 = *reinterpret_cast<const float4*>(&Ws[k][tx * 4]);
            ull b01 = pack2(b4.x, b4.y);
            ull b23 = pack2(b4.z, b4.w);
            float av[4] = {a4.x, a4.y, a4.z, a4.w};
#pragma unroll
            for (int mi = 0; mi < 4; mi++) {
                ull aa = pack2(av[mi], av[mi]);
                ffma2(acc2[mi][0], aa, b01);
                ffma2(acc2[mi][1], aa, b23);
            }
        }
        __syncthreads();
    }

#pragma unroll
    for (int mi = 0; mi < 4; mi++) {
        int m = m0 + ty * 4 + mi;
        float2 lo = unpack2(acc2[mi][0]);
        float2 hi = unpack2(acc2[mi][1]);
        float accv[4] = {lo.x, lo.y, hi.x, hi.y};
#pragma unroll
        for (int ni = 0; ni < 4; ni++) {
            int n = n0 + tx * 4 + ni;
            if (n < Npad) {
                float v = accv[ni];
                if (n < Nw) {
                    if (bias) v += bias[n];
                    if (act) v = silu_f(v);
                    if (resid) v += resid[(size_t)m * ldr + n];
                } else {
                    v = 0.f;
                }
                C[(size_t)m * ldc + n] = v;
            }
        }
    }
}

// ---------------------------------------------------------------------------
__global__ __launch_bounds__(256) void copy_feats_kernel(const float* __restrict__ feats) {
    int idx = blockIdx.x * 256 + threadIdx.x;  // over NODES*128
    int n = idx >> 7, c = idx & 127;
    g_XC[(size_t)n * 144 + c] = feats[idx];
}

// ---------------------------------------------------------------------------
// Edge kernel v2 (channel-sliced ownership, no staging): 256 threads, 8 warps,
// 4 nodes/block, 3 blocks/SM. Warp w owns channels [w*68, (w+1)*68); lane l
// owns edge l. Weights broadcast-LDS once per channel, amortized over 32
// edges. B read straight from gmem: lane streams its own edge's row as
// float4s (double-buffered). 4 channels per unrolled iteration -> 4
// independent h/silu chains. Tree reduction across warps (8KB buffer).
// ---------------------------------------------------------------------------
// byte offsets in dynamic smem:
#define OFF_WE2  0                                // ulonglong2[EPAD*4] = 34816
#define OFF_W9A  34816                            // ulonglong2[EPAD*2] = 17408
#define OFF_W9B  52224                            // ull[EPAD]          = 4352
#define OFF_AS   56576                            // float[EPAD]        = 2176
#define OFF_F2   58752                            // ull[32*6]          = 1536
#define OFF_RED  60288                            // ull[4*32*8]        = 8192
#define OFF_FLT  68480
#define FI_WC1 0
#define FI_BC1 1024
#define FI_WC2 1088
#define FI_BE2 1152
#define FI_RC  1168
#define FI_MS  1296
#define FI_CW  1808
#define FI_EBO 1840
#define FI_TOT 1872
#define EK_SMEM_BYTES (OFF_FLT + FI_TOT*4)        // 75968

__global__ __launch_bounds__(256, 3) void edge_kernel(
    const float* __restrict__ coors,
    const float* __restrict__ We1,
    const float* __restrict__ We2,
    const float* __restrict__ be2,
    const float* __restrict__ Wc1,
    const float* __restrict__ bc1,
    const float* __restrict__ Wc2,
    const float* __restrict__ bc2,
    float* __restrict__ coors_out)
{
    extern __shared__ char smc[];
    ulonglong2* We2q = (ulonglong2*)(smc + OFF_WE2);   // [c*4+p] -> outputs 4p..4p+3
    ulonglong2* W9A  = (ulonglong2*)(smc + OFF_W9A);   // [c*2+t] -> fourier terms 4t..4t+3
    ull* W9B = (ull*)(smc + OFF_W9B);                  // [c] -> (term8, 0)
    float* As  = (float*)(smc + OFF_AS);
    ull* F2u = (ull*)(smc + OFF_F2);                   // [32][6] per-edge fourier pairs
    ull* red = (ull*)(smc + OFF_RED);                  // [4][32][8] reduction buffer
    float* smf  = (float*)(smc + OFF_FLT);
    float* Wc1s = smf + FI_WC1;
    float* bc1s = smf + FI_BC1;
    float* Wc2s = smf + FI_WC2;
    float* be2s = smf + FI_BE2;
    float* rc_s = smf + FI_RC;                         // [32][4]
    float* ms   = smf + FI_MS;                         // [32][16]
    float* cw_s = smf + FI_CW;                         // [32]
    uint32_t* ebo_s = (uint32_t*)(smf + FI_EBO);       // [32]

    int tid = threadIdx.x;
    int w = tid >> 5, lane = tid & 31;
    const unsigned FULL = 0xffffffffu;
    float bc2v = bc2[0];

    // ---- weight preamble (once per block) ----
    for (int idx = tid; idx < 4 * EPAD; idx += 256) {
        int c = idx >> 2, p = idx & 3;
        ulonglong2 v; v.x = 0ull; v.y = 0ull;
        if (c < HID) {
            v.x = pack2(We2[c * 16 + 4 * p + 0], We2[c * 16 + 4 * p + 1]);
            v.y = pack2(We2[c * 16 + 4 * p + 2], We2[c * 16 + 4 * p + 3]);
        }
        We2q[idx] = v;
    }
    for (int idx = tid; idx < 2 * EPAD; idx += 256) {
        int c = idx >> 1, t = idx & 1;
        ulonglong2 v; v.x = 0ull; v.y = 0ull;
        if (c < HID) {
            v.x = pack2(We1[(size_t)(256 + 4 * t + 0) * HID + c], We1[(size_t)(256 + 4 * t + 1) * HID + c]);
            v.y = pack2(We1[(size_t)(256 + 4 * t + 2) * HID + c], We1[(size_t)(256 + 4 * t + 3) * HID + c]);
        }
        W9A[idx] = v;
    }
    for (int c = tid; c < EPAD; c += 256) {
        ull v = 0ull;
        if (c < HID) v = pack2(We1[(size_t)264 * HID + c], 0.f);
        W9B[c] = v;
    }
    for (int idx = tid; idx < 16 * 64; idx += 256) Wc1s[idx] = Wc1[idx];
    if (tid < 64) { bc1s[tid] = bc1[tid]; Wc2s[tid] = Wc2[tid]; }
    if (tid >= 64 && tid < 80) be2s[tid - 64] = be2[tid - 64];
    __syncthreads();

#pragma unroll 1
    for (int nn = 0; nn < 4; nn++) {
        int node = blockIdx.x * 4 + nn;
        int b = node >> 12, i = node & (NNODES - 1);
        const float* cb = coors + (size_t)b * NNODES * 3;
        const float* Ap = g_A + (size_t)node * EPAD;

        // ---- per-node setup: A row, fourier pairs, rel coords, B offsets ----
        for (int idx = tid; idx < EPAD; idx += 256) As[idx] = Ap[idx];
        if (tid < 32) {
            int e = tid;
            int j = g_knn[(size_t)node * KNN + e];
            ebo_s[e] = (uint32_t)(b * NNODES + j);
            float dx = cb[3 * i + 0] - cb[3 * j + 0];
            float dy = cb[3 * i + 1] - cb[3 * j + 1];
            float dz = cb[3 * i + 2] - cb[3 * j + 2];
            float d = dist2_f(dx, dy, dz);
            rc_s[e * 4 + 0] = dx; rc_s[e * 4 + 1] = dy; rc_s[e * 4 + 2] = dz; rc_s[e * 4 + 3] = 0.f;
            float s0, c0, s1, c1, s2, c2, s3, c3;
            sincosf(d,          &s0, &c0);
            sincosf(d * 0.5f,   &s1, &c1);
            sincosf(d * 0.25f,  &s2, &c2);
            sincosf(d * 0.125f, &s3, &c3);
            F2u[e * 6 + 0] = pack2(s0, s1);
            F2u[e * 6 + 1] = pack2(s2, s3);
            F2u[e * 6 + 2] = pack2(c0, c1);
            F2u[e * 6 + 3] = pack2(c2, c3);
            F2u[e * 6 + 4] = pack2(d, 0.f);
        }
        __syncthreads();

        // lane owns edge = lane; warp owns channels [w*68, w*68+68)
        ull fp[5];
#pragma unroll
        for (int t = 0; t < 5; t++) fp[t] = F2u[lane * 6 + t];

        int c0base = w * 68;
        const float* Bp = g_B + (size_t)ebo_s[lane] * EPAD + c0base;

        ull m[8];
#pragma unroll
        for (int p = 0; p < 8; p++) m[p] = 0ull;

        float4 bbuf0 = *reinterpret_cast<const float4*>(Bp + 0);
        float4 bbuf1 = *reinterpret_cast<const float4*>(Bp + 4);

#pragma unroll
        for (int it = 0; it < 17; it++) {
            float4 bv = (it & 1) ? bbuf1 : bbuf0;
            if (it + 2 < 17) {
                float4 nxt = *reinterpret_cast<const float4*>(Bp + (it + 2) * 4);
                if (it & 1) bbuf1 = nxt; else bbuf0 = nxt;
            }
            int c = c0base + it * 4;
            float4 av = *reinterpret_cast<const float4*>(&As[c]);   // broadcast

            float aa[4] = {av.x, av.y, av.z, av.w};
            float bb[4] = {bv.x, bv.y, bv.z, bv.w};
#pragma unroll
            for (int u = 0; u < 4; u++) {
                int cu = c + u;
                ulonglong2 w9a0 = W9A[cu * 2 + 0];
                ulonglong2 w9a1 = W9A[cu * 2 + 1];
                ull        w9b  = W9B[cu];

                ull ha = pack2(aa[u] + bb[u], 0.f);
                ull hb = 0ull;
                ffma2(ha, fp[0], w9a0.x);
                ffma2(hb, fp[1], w9a0.y);
                ffma2(ha, fp[2], w9a1.x);
                ffma2(hb, fp[3], w9a1.y);
                ffma2(ha, fp[4], w9b);
                float2 hv = unpack2(fadd2(ha, hb));
                float sh = silu_f(hv.x + hv.y);
                ull shp = pack2(sh, sh);

                ulonglong2 q0 = We2q[cu * 4 + 0];
                ulonglong2 q1 = We2q[cu * 4 + 1];
                ulonglong2 q2 = We2q[cu * 4 + 2];
                ulonglong2 q3 = We2q[cu * 4 + 3];
                ffma2(m[0], shp, q0.x); ffma2(m[1], shp, q0.y);
                ffma2(m[2], shp, q1.x); ffma2(m[3], shp, q1.y);
                ffma2(m[4], shp, q2.x); ffma2(m[5], shp, q2.y);
                ffma2(m[6], shp, q3.x); ffma2(m[7], shp, q3.y);
            }
        }

        // ---- tree reduction across 8 warps (buffer = 4*32*8 ull) ----
        if (w >= 4) {
            int base = ((w - 4) * 32 + lane) * 8;
#pragma unroll
            for (int p = 0; p < 8; p++) red[base + p] = m[p];
        }
        __syncthreads();
        if (w < 4) {
            int base = (w * 32 + lane) * 8;
#pragma unroll
            for (int p = 0; p < 8; p++) m[p] = fadd2(m[p], red[base + p]);
        }
        __syncthreads();
        if (w >= 2 && w < 4) {
            int base = ((w - 2) * 32 + lane) * 8;
#pragma unroll
            for (int p = 0; p < 8; p++) red[base + p] = m[p];
        }
        __syncthreads();
        if (w < 2) {
            int base = (w * 32 + lane) * 8;
#pragma unroll
            for (int p = 0; p < 8; p++) m[p] = fadd2(m[p], red[base + p]);
        }
        __syncthreads();
        if (w == 1) {
            int base = lane * 8;
#pragma unroll
            for (int p = 0; p < 8; p++) red[base + p] = m[p];
        }
        __syncthreads();
        if (w == 0) {
            int base = lane * 8;
#pragma unroll
            for (int p = 0; p < 8; p++) {
                float2 v = unpack2(fadd2(m[p], red[base + p]));
                ms[lane * 16 + 2 * p + 0] = silu_f(v.x + be2s[2 * p + 0]);
                ms[lane * 16 + 2 * p + 1] = silu_f(v.y + be2s[2 * p + 1]);
            }
        }
        __syncthreads();

        // ---- coors MLP: 8 threads per edge ----
        {
            int e = tid >> 3, li = tid & 7;
            float wpart = 0.f;
#pragma unroll
            for (int q = 0; q < 8; q++) {
                int l = li * 8 + q;
                float u = bc1s[l];
#pragma unroll
                for (int k = 0; k < 16; k++)
                    u = fmaf(ms[e * 16 + k], Wc1s[k * 64 + l], u);
                wpart = fmaf(silu_f(u), Wc2s[l], wpart);
            }
            wpart += __shfl_xor_sync(FULL, wpart, 1);
            wpart += __shfl_xor_sync(FULL, wpart, 2);
            wpart += __shfl_xor_sync(FULL, wpart, 4);
            if (li == 0) cw_s[e] = wpart + bc2v;
        }
        __syncthreads();

        // ---- m_i (threads 0-15) and coors_out (warp 1) ----
        if (tid < 16) {
            float s = 0.f;
#pragma unroll 8
            for (int e2 = 0; e2 < 32; e2++) s += ms[e2 * 16 + tid];
            g_XC[(size_t)node * 144 + 128 + tid] = s;
        }
        if (w == 1) {
            int e2 = lane;
            float wv = cw_s[e2];
            float px = wv * rc_s[e2 * 4 + 0];
            float py = wv * rc_s[e2 * 4 + 1];
            float pz = wv * rc_s[e2 * 4 + 2];
#pragma unroll
            for (int off = 16; off > 0; off >>= 1) {
                px += __shfl_down_sync(FULL, px, off);
                py += __shfl_down_sync(FULL, py, off);
                pz += __shfl_down_sync(FULL, pz, off);
            }
            if (lane == 0) {
                float* co = coors_out + (size_t)node * 3;
                co[0] = cb[3 * i + 0] + px;
                co[1] = cb[3 * i + 1] + py;
                co[2] = cb[3 * i + 2] + pz;
            }
        }
        __syncthreads();
    }
}

// ---------------------------------------------------------------------------
extern "C" void kernel_launch(void* const* d_in, const int* in_sizes, int n_in,
                              void* d_out, int out_size) {
    const float* feats = (const float*)d_in[0];
    const float* coors = (const float*)d_in[1];
    const float* We1   = (const float*)d_in[2];
    const float* be1   = (const float*)d_in[3];
    const float* We2   = (const float*)d_in[4];
    const float* be2   = (const float*)d_in[5];
    const float* Wc1   = (const float*)d_in[6];
    const float* bc1   = (const float*)d_in[7];
    const float* Wc2   = (const float*)d_in[8];
    const float* bc2   = (const float*)d_in[9];
    const float* Wn1   = (const float*)d_in[10];
    const float* bn1   = (const float*)d_in[11];
    const float* Wn2   = (const float*)d_in[12];
    const float* bn2   = (const float*)d_in[13];
    float* out = (float*)d_out;
    float* node_out  = out;
    float* coors_out = out + NODE_OUT_ELEMS;

    float *pA, *pB, *pXC, *pH1;
    cudaGetSymbolAddress((void**)&pA, g_A);
    cudaGetSymbolAddress((void**)&pB, g_B);
    cudaGetSymbolAddress((void**)&pXC, g_XC);
    cudaGetSymbolAddress((void**)&pH1, g_H1);

    cudaFuncSetAttribute(edge_kernel, cudaFuncAttributeMaxDynamicSharedMemorySize, EK_SMEM_BYTES);

    // 1) KNN
    knn_kernel<<<NODES / 8, 256>>>(coors);

    // 2) A = feats @ We1[0:128,:] + be1 ; B = feats @ We1[128:256,:]  (pad->544)
    gemm_kernel<<<dim3(9, NODES / 64), 256>>>(feats, DIMF, We1, HID, be1, nullptr, 0,
                                              pA, EPAD, HID, EPAD, DIMF, 0);
    gemm_kernel<<<dim3(9, NODES / 64), 256>>>(feats, DIMF, We1 + 128 * HID, HID, nullptr, nullptr, 0,
                                              pB, EPAD, HID, EPAD, DIMF, 0);

    // 3) edges: m_ij -> m_i (XC[:,128:144]), coors_out
    edge_kernel<<<NODES / 4, 256, EK_SMEM_BYTES>>>(coors, We1, We2, be2,
                                                   Wc1, bc1, Wc2, bc2, coors_out);

    // 4) XC[:, 0:128] = feats
    copy_feats_kernel<<<(NODES * DIMF) / 256, 256>>>(feats);

    // 5) node MLP
    gemm_kernel<<<dim3(4, NODES / 64), 256>>>(pXC, 144, Wn1, 256, bn1, nullptr, 0,
                                              pH1, 256, 256, 256, 144, 1);
    gemm_kernel<<<dim3(2, NODES / 64), 256>>>(pH1, 256, Wn2, DIMF, bn2, feats, DIMF,
                                              node_out, DIMF, DIMF, DIMF, 256, 0);
}